// round 11
// baseline (speedup 1.0000x reference)
#include <cuda_runtime.h>
#include <math_constants.h>

// Scratch + sync state (no device allocs allowed)
__device__ float g_map[32 * 2 * 64 * 64];   // [b][2][4096]
__device__ float g_scale[32 * 64 * 64];     // [b][4096]
__device__ unsigned int g_work;
__device__ unsigned int g_k1done[32];       // K1 items completed per image (target 32)
__device__ unsigned int g_k2done[32];       // K2 items completed per image (target 16)

#define NB 32
#define NC 256
#define HW 4096
#define HW4 1024

// schedule: window g = {32 K1 items(img g), 16 K2 items(img g-1), 256 K3 items(img g-2)}
// interleaved as 16 groups of 19 = [2xK1, 1xK2, 16xK3]
#define WIN_ITEMS 304
#define N_WINDOWS 34
#define TOTAL_ITEMS (WIN_ITEMS * N_WINDOWS)

__global__ void init_kernel() {
    if (threadIdx.x == 0) g_work = 0;
    if (threadIdx.x < 32) { g_k1done[threadIdx.x] = 0; g_k2done[threadIdx.x] = 0; }
}

// ---- K1 item: image b, local 0..31 -> 32 float4 pixels, all 256 channels ----
__device__ __forceinline__ void k1_item(const float* __restrict__ x, int b, int local,
                                        float4 (*smax)[32], float4 (*ssum)[32]) {
    int lane = threadIdx.x & 31;
    int wrp  = threadIdx.x >> 5;
    int p4   = (local << 5) + lane;

    const float4* __restrict__ xv = reinterpret_cast<const float4*>(x);
    size_t base = (size_t)b * (NC * HW4) + (size_t)(wrp << 5) * HW4 + p4;

    float4 mx = make_float4(-CUDART_INF_F, -CUDART_INF_F, -CUDART_INF_F, -CUDART_INF_F);
    float4 sm = make_float4(0.f, 0.f, 0.f, 0.f);
    #pragma unroll
    for (int c = 0; c < 32; c++) {
        float4 v = __ldg(&xv[base + (size_t)c * HW4]);
        mx.x = fmaxf(mx.x, v.x); mx.y = fmaxf(mx.y, v.y);
        mx.z = fmaxf(mx.z, v.z); mx.w = fmaxf(mx.w, v.w);
        sm.x += v.x; sm.y += v.y; sm.z += v.z; sm.w += v.w;
    }
    smax[wrp][lane] = mx;
    ssum[wrp][lane] = sm;
    __syncthreads();

    if (wrp == 0) {
        float4 m = smax[0][lane];
        float4 s = ssum[0][lane];
        #pragma unroll
        for (int w = 1; w < 8; w++) {
            float4 m2 = smax[w][lane];
            float4 s2 = ssum[w][lane];
            m.x = fmaxf(m.x, m2.x); m.y = fmaxf(m.y, m2.y);
            m.z = fmaxf(m.z, m2.z); m.w = fmaxf(m.w, m2.w);
            s.x += s2.x; s.y += s2.y; s.z += s2.z; s.w += s2.w;
        }
        const float inv = 1.0f / (float)NC;
        s.x *= inv; s.y *= inv; s.z *= inv; s.w *= inv;
        float4* mv = reinterpret_cast<float4*>(g_map);
        mv[(size_t)b * 2048 + p4]        = m;
        mv[(size_t)b * 2048 + 1024 + p4] = s;
        __threadfence();
    }
    __syncthreads();
    if (threadIdx.x == 0) atomicAdd(&g_k1done[b], 1u);
}

// ---- K2 item: image b, local 0..15 -> 256 pixels of conv+sigmoid ----
__device__ __forceinline__ void k2_item(const float* __restrict__ w, int b, int local,
                                        float* sw) {
    if (threadIdx.x == 0) {
        unsigned int v;
        while ((v = atomicAdd(&g_k1done[b], 0u)) < 32u) __nanosleep(64);
        __threadfence();
    }
    if (threadIdx.x < 98) sw[threadIdx.x] = __ldg(&w[threadIdx.x]);
    __syncthreads();

    int hw = (local << 8) + threadIdx.x;   // 0..4095
    int h  = hw >> 6;
    int wc = hw & 63;
    const float* __restrict__ mp = g_map + (size_t)b * 2 * HW;

    float acc = 0.f;
    #pragma unroll
    for (int ky = 0; ky < 7; ky++) {
        int hy = h + ky - 3;
        if (hy < 0 || hy >= 64) continue;
        #pragma unroll
        for (int kx = 0; kx < 7; kx++) {
            int wx = wc + kx - 3;
            if (wx < 0 || wx >= 64) continue;
            int q = hy * 64 + wx;
            acc = fmaf(sw[ky * 7 + kx],      __ldg(&mp[q]),      acc);
            acc = fmaf(sw[49 + ky * 7 + kx], __ldg(&mp[HW + q]), acc);
        }
    }
    g_scale[(size_t)b * HW + hw] = 1.0f / (1.0f + __expf(-acc));
    __threadfence();
    __syncthreads();
    if (threadIdx.x == 0) atomicAdd(&g_k2done[b], 1u);
}

// ---- K3 item: image b, local 0..255 -> 1024 float4 of out = x*scale ----
__device__ __forceinline__ void k3_item(const float* __restrict__ x,
                                        float* __restrict__ out, int b, int local) {
    if (threadIdx.x == 0) {
        while (atomicAdd(&g_k2done[b], 0u) < 16u) __nanosleep(64);
        __threadfence();
    }
    __syncthreads();

    const float4* __restrict__ xv = reinterpret_cast<const float4*>(x);
    const float4* __restrict__ sv = reinterpret_cast<const float4*>(g_scale);
    float4* __restrict__ ov = reinterpret_cast<float4*>(out);

    size_t blk = ((size_t)b * 256 + local) << 10;   // 1024 float4 per item

    float4 v[4], s[4];
    #pragma unroll
    for (int k = 0; k < 4; k++) {
        size_t i = blk + k * 256 + threadIdx.x;
        v[k] = __ldcs(&xv[i]);
        s[k] = __ldg(&sv[(size_t)b * HW4 + (i & 1023)]);
    }
    #pragma unroll
    for (int k = 0; k < 4; k++) {
        size_t i = blk + k * 256 + threadIdx.x;
        v[k].x *= s[k].x; v[k].y *= s[k].y; v[k].z *= s[k].z; v[k].w *= s[k].w;
        __stcs(&ov[i], v[k]);
    }
}

// ---- persistent dataflow kernel ----
__global__ __launch_bounds__(256, 6) void pipe_kernel(const float* __restrict__ x,
                                                      const float* __restrict__ w,
                                                      float* __restrict__ out) {
    __shared__ float4 smax[8][32];
    __shared__ float4 ssum[8][32];
    __shared__ float sw[98];
    __shared__ unsigned int s_wid;

    for (;;) {
        if (threadIdx.x == 0) s_wid = atomicAdd(&g_work, 1u);
        __syncthreads();
        unsigned int wid = s_wid;
        __syncthreads();
        if (wid >= TOTAL_ITEMS) break;

        int win = wid / WIN_ITEMS;
        int r   = wid % WIN_ITEMS;
        int q   = r / 19;
        int t   = r % 19;

        if (t < 2) {                       // K1, image = win
            int b = win;
            if (b < NB) k1_item(x, b, q * 2 + t, smax, ssum);
        } else if (t == 2) {               // K2, image = win-1
            int b = win - 1;
            if (b >= 0 && b < NB) k2_item(w, b, q, sw);
        } else {                           // K3, image = win-2
            int b = win - 2;
            if (b >= 0 && b < NB) k3_item(x, out, b, q * 16 + (t - 3));
        }
    }
}

extern "C" void kernel_launch(void* const* d_in, const int* in_sizes, int n_in,
                              void* d_out, int out_size) {
    const float* x = (const float*)d_in[0];
    const float* w = (const float*)d_in[1];
    float* out = (float*)d_out;

    init_kernel<<<1, 64>>>();
    // 888 = 6 blocks/SM * 148 SMs: entire grid co-resident -> spin-waits are
    // deadlock-free; queue interleaves K1 reads with K3 writes continuously.
    pipe_kernel<<<888, 256>>>(x, w, out);
}

// round 12
// speedup vs baseline: 1.6763x; 1.6763x over previous
#include <cuda_runtime.h>
#include <math_constants.h>

// Scratch (no device allocs allowed)
__device__ float g_map[32 * 2 * 64 * 64];   // [b][2][4096]
__device__ float g_scale[32 * 64 * 64];     // [b][4096]

#define NB 32
#define NC 256
#define HW 4096
#define HW4 1024

// ---------------- K1 body: channel max+mean for 32 float4 pixels ----------------
__device__ __forceinline__ void k1_body(const float* __restrict__ x, int local, int b0) {
    __shared__ float4 smax[8][32];
    __shared__ float4 ssum[8][32];

    int lane = threadIdx.x & 31;
    int wrp  = threadIdx.x >> 5;
    int b    = b0 + (local >> 5);
    int p4   = ((local & 31) << 5) + lane;

    const float4* __restrict__ xv = reinterpret_cast<const float4*>(x);
    size_t base = (size_t)b * (NC * HW4) + (size_t)(wrp << 5) * HW4 + p4;

    float4 mx = make_float4(-CUDART_INF_F, -CUDART_INF_F, -CUDART_INF_F, -CUDART_INF_F);
    float4 sm = make_float4(0.f, 0.f, 0.f, 0.f);
    #pragma unroll
    for (int c = 0; c < 32; c++) {
        float4 v = __ldg(&xv[base + (size_t)c * HW4]);
        mx.x = fmaxf(mx.x, v.x); mx.y = fmaxf(mx.y, v.y);
        mx.z = fmaxf(mx.z, v.z); mx.w = fmaxf(mx.w, v.w);
        sm.x += v.x; sm.y += v.y; sm.z += v.z; sm.w += v.w;
    }
    smax[wrp][lane] = mx;
    ssum[wrp][lane] = sm;
    __syncthreads();

    if (wrp == 0) {
        float4 m = smax[0][lane];
        float4 s = ssum[0][lane];
        #pragma unroll
        for (int w = 1; w < 8; w++) {
            float4 m2 = smax[w][lane];
            float4 s2 = ssum[w][lane];
            m.x = fmaxf(m.x, m2.x); m.y = fmaxf(m.y, m2.y);
            m.z = fmaxf(m.z, m2.z); m.w = fmaxf(m.w, m2.w);
            s.x += s2.x; s.y += s2.y; s.z += s2.z; s.w += s2.w;
        }
        const float inv = 1.0f / (float)NC;
        s.x *= inv; s.y *= inv; s.z *= inv; s.w *= inv;
        float4* mv = reinterpret_cast<float4*>(g_map);
        mv[(size_t)b * 2048 + p4]        = m;
        mv[(size_t)b * 2048 + 1024 + p4] = s;
    }
}

// ---------------- K3 body: one channel plane (1024 float4) of out = x*scale ----------------
__device__ __forceinline__ void k3_body(const float* __restrict__ x,
                                        float* __restrict__ out, size_t plane) {
    const float4* __restrict__ xv = reinterpret_cast<const float4*>(x);
    const float4* __restrict__ sv = reinterpret_cast<const float4*>(g_scale);
    float4* __restrict__ ov = reinterpret_cast<float4*>(out);

    size_t blk = plane << 10;             // 1024 float4
    int b = (int)(plane >> 8);            // 256 planes per image

    float4 v[4], s[4];
    #pragma unroll
    for (int k = 0; k < 4; k++) {
        size_t i = blk + k * 256 + threadIdx.x;
        v[k] = __ldcs(&xv[i]);
        s[k] = __ldg(&sv[(size_t)b * HW4 + (i & 1023)]);
    }
    #pragma unroll
    for (int k = 0; k < 4; k++) {
        size_t i = blk + k * 256 + threadIdx.x;
        v[k].x *= s[k].x; v[k].y *= s[k].y; v[k].z *= s[k].z; v[k].w *= s[k].w;
        __stcs(&ov[i], v[k]);
    }
}

// ---------------- standalone kernels ----------------
__global__ __launch_bounds__(256) void reduce_kernel(const float* __restrict__ x, int b0) {
    k1_body(x, blockIdx.x, b0);
}

__global__ __launch_bounds__(256) void conv_kernel(const float* __restrict__ w, int b0) {
    __shared__ float sw[98];
    if (threadIdx.x < 98) sw[threadIdx.x] = w[threadIdx.x];
    __syncthreads();

    int pid = blockIdx.x * blockDim.x + threadIdx.x;   // 0..65535 local
    int b  = b0 + (pid >> 12);
    int hw = pid & 4095;
    int h  = hw >> 6;
    int wc = hw & 63;

    const float* __restrict__ mp = g_map + (size_t)b * 2 * HW;

    float acc = 0.f;
    #pragma unroll
    for (int ky = 0; ky < 7; ky++) {
        int hy = h + ky - 3;
        if (hy < 0 || hy >= 64) continue;
        #pragma unroll
        for (int kx = 0; kx < 7; kx++) {
            int wx = wc + kx - 3;
            if (wx < 0 || wx >= 64) continue;
            int q = hy * 64 + wx;
            acc = fmaf(sw[ky * 7 + kx],      __ldg(&mp[q]),      acc);
            acc = fmaf(sw[49 + ky * 7 + kx], __ldg(&mp[HW + q]), acc);
        }
    }
    g_scale[(size_t)b * HW + hw] = 1.0f / (1.0f + __expf(-acc));
}

__global__ __launch_bounds__(256) void mul_kernel(const float* __restrict__ x,
                                                  float* __restrict__ out, int plane0) {
    k3_body(x, out, (size_t)plane0 + blockIdx.x);
}

// ---------------- mixed overlap kernel: K1(second half) + K3(first half) ----------------
// bid [0,512): K1 blocks for images 16-31 (long blocks first -> no tail);
// bid [512,4608): K3 planes 0..4095 (images 0-15). No internal dependencies.
__global__ __launch_bounds__(256) void mix_kernel(const float* __restrict__ x,
                                                  float* __restrict__ out) {
    int bid = blockIdx.x;
    if (bid < 512) {
        k1_body(x, bid, 16);
    } else {
        k3_body(x, out, (size_t)(bid - 512));
    }
}

extern "C" void kernel_launch(void* const* d_in, const int* in_sizes, int n_in,
                              void* d_out, int out_size) {
    const float* x = (const float*)d_in[0];
    const float* w = (const float*)d_in[1];
    float* out = (float*)d_out;

    reduce_kernel<<<512, 256>>>(x, 0);        // K1 imgs 0-15
    conv_kernel<<<256, 256>>>(w, 0);          // K2 imgs 0-15
    mix_kernel<<<4608, 256>>>(x, out);        // K1 imgs 16-31  ||  K3 imgs 0-15
    conv_kernel<<<256, 256>>>(w, 16);         // K2 imgs 16-31
    mul_kernel<<<4096, 256>>>(x, out, 4096);  // K3 imgs 16-31
}

// round 14
// speedup vs baseline: 1.8078x; 1.0785x over previous
#include <cuda_runtime.h>
#include <math_constants.h>

// Scratch + sync (no device allocs allowed)
__device__ float g_map[32 * 2 * 64 * 64];   // [b][2][4096]
__device__ float g_scale[32 * 64 * 64];     // [b][4096]
__device__ unsigned int g_k1done[32];       // K1 blocks done per image (target 32)

#define NB 32
#define NC 256
#define HW 4096
#define HW4 1024

__global__ void init_kernel() {
    if (threadIdx.x < 32) g_k1done[threadIdx.x] = 0;
}

// ---- K1 body: channel max+mean for 32 float4 pixels (block `local`, half b0) ----
__device__ __forceinline__ void k1_body(const float* __restrict__ x, int local, int b0) {
    __shared__ float4 smax[8][32];
    __shared__ float4 ssum[8][32];

    int lane = threadIdx.x & 31;
    int wrp  = threadIdx.x >> 5;
    int b    = b0 + (local >> 5);
    int p4   = ((local & 31) << 5) + lane;

    const float4* __restrict__ xv = reinterpret_cast<const float4*>(x);
    size_t base = (size_t)b * (NC * HW4) + (size_t)(wrp << 5) * HW4 + p4;

    float4 mx = make_float4(-CUDART_INF_F, -CUDART_INF_F, -CUDART_INF_F, -CUDART_INF_F);
    float4 sm = make_float4(0.f, 0.f, 0.f, 0.f);
    #pragma unroll
    for (int c = 0; c < 32; c++) {
        float4 v = __ldg(&xv[base + (size_t)c * HW4]);
        mx.x = fmaxf(mx.x, v.x); mx.y = fmaxf(mx.y, v.y);
        mx.z = fmaxf(mx.z, v.z); mx.w = fmaxf(mx.w, v.w);
        sm.x += v.x; sm.y += v.y; sm.z += v.z; sm.w += v.w;
    }
    smax[wrp][lane] = mx;
    ssum[wrp][lane] = sm;
    __syncthreads();

    if (wrp == 0) {
        float4 m = smax[0][lane];
        float4 s = ssum[0][lane];
        #pragma unroll
        for (int w = 1; w < 8; w++) {
            float4 m2 = smax[w][lane];
            float4 s2 = ssum[w][lane];
            m.x = fmaxf(m.x, m2.x); m.y = fmaxf(m.y, m2.y);
            m.z = fmaxf(m.z, m2.z); m.w = fmaxf(m.w, m2.w);
            s.x += s2.x; s.y += s2.y; s.z += s2.z; s.w += s2.w;
        }
        const float inv = 1.0f / (float)NC;
        s.x *= inv; s.y *= inv; s.z *= inv; s.w *= inv;
        float4* mv = reinterpret_cast<float4*>(g_map);
        mv[(size_t)b * 2048 + p4]        = m;
        mv[(size_t)b * 2048 + 1024 + p4] = s;
        __threadfence();
    }
    __syncthreads();
    if (threadIdx.x == 0) atomicAdd(&g_k1done[b], 1u);
}

// ---- K2 body: conv7x7+sigmoid, 256 pixels (item `local` of 256, half b0) ----
// Spins ONLY on K1 blocks launched in the SAME kernel at lower bids; both
// phases fit in wave 1 (<=768 blocks < 1184 resident) -> deadlock-free.
__device__ __forceinline__ void k2_body(const float* __restrict__ w, int local, int b0) {
    __shared__ float sw[98];
    int b  = b0 + (local >> 4);
    int hw = ((local & 15) << 8) + threadIdx.x;

    if (threadIdx.x == 0) {
        while (atomicAdd(&g_k1done[b], 0u) < 32u) __nanosleep(64);
        __threadfence();
    }
    if (threadIdx.x < 98) sw[threadIdx.x] = __ldg(&w[threadIdx.x]);
    __syncthreads();

    int h  = hw >> 6;
    int wc = hw & 63;
    const float* __restrict__ mp = g_map + (size_t)b * 2 * HW;

    float acc = 0.f;
    #pragma unroll
    for (int ky = 0; ky < 7; ky++) {
        int hy = h + ky - 3;
        if (hy < 0 || hy >= 64) continue;
        #pragma unroll
        for (int kx = 0; kx < 7; kx++) {
            int wx = wc + kx - 3;
            if (wx < 0 || wx >= 64) continue;
            int q = hy * 64 + wx;
            acc = fmaf(sw[ky * 7 + kx],      __ldg(&mp[q]),      acc);
            acc = fmaf(sw[49 + ky * 7 + kx], __ldg(&mp[HW + q]), acc);
        }
    }
    g_scale[(size_t)b * HW + hw] = 1.0f / (1.0f + __expf(-acc));
}

// ---- K3 body: one channel plane (1024 float4) of out = x*scale; no deps ----
__device__ __forceinline__ void k3_body(const float* __restrict__ x,
                                        float* __restrict__ out, size_t plane) {
    const float4* __restrict__ xv = reinterpret_cast<const float4*>(x);
    const float4* __restrict__ sv = reinterpret_cast<const float4*>(g_scale);
    float4* __restrict__ ov = reinterpret_cast<float4*>(out);

    size_t blk = plane << 10;
    int b = (int)(plane >> 8);

    float4 v[4], s[4];
    #pragma unroll
    for (int k = 0; k < 4; k++) {
        size_t i = blk + k * 256 + threadIdx.x;
        v[k] = __ldcs(&xv[i]);
        s[k] = __ldg(&sv[(size_t)b * HW4 + (i & 1023)]);
    }
    #pragma unroll
    for (int k = 0; k < 4; k++) {
        size_t i = blk + k * 256 + threadIdx.x;
        v[k].x *= s[k].x; v[k].y *= s[k].y; v[k].z *= s[k].z; v[k].w *= s[k].w;
        __stcs(&ov[i], v[k]);
    }
}

// ---- L1: K1(h0) + K2(h0)  (768 blocks, all wave-1 resident) ----
__global__ __launch_bounds__(256) void phaseA_kernel(const float* __restrict__ x,
                                                     const float* __restrict__ w) {
    int bid = blockIdx.x;
    if (bid < 512) k1_body(x, bid, 0);
    else           k2_body(w, bid - 512, 0);
}

// ---- L2: K1(h1) + K2(h1)  ||  K3(h0)  (4864 blocks) ----
// bids [0,512): K1 imgs 16-31; [512,768): K2 imgs 16-31 (same-launch spin,
// wave-1 safe); [768,4864): K3 planes 0..4095 (deps satisfied by L1).
__global__ __launch_bounds__(256) void phaseB_kernel(const float* __restrict__ x,
                                                     const float* __restrict__ w,
                                                     float* __restrict__ out) {
    int bid = blockIdx.x;
    if (bid < 512)      k1_body(x, bid, 16);
    else if (bid < 768) k2_body(w, bid - 512, 16);
    else                k3_body(x, out, (size_t)(bid - 768));
}

// ---- L3: K3(h1) ----
__global__ __launch_bounds__(256) void phaseC_kernel(const float* __restrict__ x,
                                                     float* __restrict__ out) {
    k3_body(x, out, (size_t)blockIdx.x + 4096);
}

extern "C" void kernel_launch(void* const* d_in, const int* in_sizes, int n_in,
                              void* d_out, int out_size) {
    const float* x = (const float*)d_in[0];
    const float* w = (const float*)d_in[1];
    float* out = (float*)d_out;

    init_kernel<<<1, 32>>>();
    phaseA_kernel<<<768, 256>>>(x, w);
    phaseB_kernel<<<4864, 256>>>(x, w, out);
    phaseC_kernel<<<4096, 256>>>(x, out);
}